// round 16
// baseline (speedup 1.0000x reference)
#include <cuda_runtime.h>
#include <cuda_fp16.h>
#include <cstdint>

// Fused batched GCN, one CTA per graph (512 x 100 nodes, deg 16).
// 512 thr/CTA, __launch_bounds__(512,2) -> 2 CTAs/SM = 32 warps, 64-reg cap.
// Warp owns rows {warp + 16*i, i<7}. feat/W1 fp16, W2 fp32, h1 overlays A,
// t overlays h1. GEMM1 pass-0 h results parked as fp16 in the dead feat
// buffer (saves the 16-reg carry). GEMMs: packed fma.rn.f32x2 over k.
// Heads: softmax over a length-1 token == 1 -> Z=(x@Wv^T)@Wo^T; Wq/Wk dead.

#define NPG 100
#define DEG 16
#define DIN 100
#define H1D 100
#define DG  20
#define P2D 200
#define P3D 100
#define PW1 27     // u64 pitch of fp16 W1 (odd -> conflict-free LDS.64)
#define PW2 102    // float pitch of fp32 W2 (u64 stride 51, odd -> CF)

// ---- shared memory layout (4-byte element offsets) ----
#define OFF_XH   0          // 5000  feat fp16 (10000 halves); h16 park overlay
#define OFF_A    5000       // 10000 A (pitch 100); h1 then t overlay rows
#define OFF_W1   15000      // 5400  W1 fp16 (100 x 27 u64)
#define OFF_W2   20400      // 2040  W2 fp32 (20 x 102)
#define OFF_E8   22440      // 400   edges u8 packed
#define OFF_SF   22840      // 200
#define OFF_X3   23040      // 104
#define OFF_PART 23144      // 16*20 = 320
#define OFF_VP2  23464      // 512
#define OFF_VP3  23976      // 512
#define OFF_VV   24488      // 64
#define OFF_HG2  24552      // 24
#define OFF_O10  24576      // 16
#define SMEM_ELEMS 24592
#define SMEM_BYTES (SMEM_ELEMS * 4)   // 98368 B -> 2 CTAs/SM

typedef unsigned long long u64;
typedef unsigned int u32;

static __device__ __forceinline__ void ffma2(u64& d, u64 a, u64 b) {
    asm("fma.rn.f32x2 %0, %1, %2, %0;" : "+l"(d) : "l"(a), "l"(b));
}
static __device__ __forceinline__ void lds_v2u64(u64& a, u64& b, const float* p) {
    asm("ld.shared.v2.u64 {%0,%1}, [%2];"
        : "=l"(a), "=l"(b) : "l"(__cvta_generic_to_shared(p)));
}
static __device__ __forceinline__ void lds_v2u32(u32& a, u32& b, const void* p) {
    asm("ld.shared.v2.u32 {%0,%1}, [%2];"
        : "=r"(a), "=r"(b) : "l"(__cvta_generic_to_shared(p)));
}
static __device__ __forceinline__ float hsum2(u64 v) {
    float lo = __uint_as_float((u32)(v & 0xffffffffu));
    float hi = __uint_as_float((u32)(v >> 32));
    return lo + hi;
}
static __device__ __forceinline__ u64 pack2(float lo, float hi) {
    return (u64)__float_as_uint(lo) | ((u64)__float_as_uint(hi) << 32);
}
static __device__ __forceinline__ u64 h2w(u32 v) {   // fp16 pair -> f32x2
    __half2 h = *reinterpret_cast<__half2*>(&v);
    float2 f = __half22float2(h);
    return pack2(f.x, f.y);
}
static __device__ __forceinline__ __half2 asH2(u32 v) {
    return *reinterpret_cast<__half2*>(&v);
}

__global__ __launch_bounds__(512, 2)
void net_kernel(const float* __restrict__ feat,
                const int*   __restrict__ edge_src,
                const float* __restrict__ self_feat,
                const float* __restrict__ x3d,
                const float* __restrict__ W1,  const float* __restrict__ b1,
                const float* __restrict__ W2,  const float* __restrict__ b2,
                const float* __restrict__ Wv2, const float* __restrict__ Wo2,
                const float* __restrict__ g2,  const float* __restrict__ be2,
                const float* __restrict__ Wv3, const float* __restrict__ Wo3,
                const float* __restrict__ g3,  const float* __restrict__ be3,
                const float* __restrict__ Wf1, const float* __restrict__ bf1,
                const float* __restrict__ Wf2, const float* __restrict__ bf2,
                float* __restrict__ out)
{
    extern __shared__ float sm[];
    char*  sXh  = (char*)(sm + OFF_XH);      // fp16 feat, 200 B/row
    u32*   sH16 = (u32*)(sm + OFF_XH);       // pass-0 h park (100x32 u32)
    float* sA   = sm + OFF_A;                // A -> h1 -> t (per-row overlay)
    u64*   sW1u = (u64*)(sm + OFF_W1);
    float* sW2f = sm + OFF_W2;
    u32*   sE8  = (u32*)(sm + OFF_E8);
    float* sSf  = sm + OFF_SF;
    float* sX3  = sm + OFF_X3;
    float* sPart= sm + OFF_PART;
    float* sVp2 = sm + OFF_VP2;
    float* sVp3 = sm + OFF_VP3;
    float* sVv  = sm + OFF_VV;
    float* sHg2 = sm + OFF_HG2;
    float* sO10 = sm + OFF_O10;

    const int g    = blockIdx.x;
    const int tid  = threadIdx.x;
    const int warp = tid >> 5;
    const int lane = tid & 31;

    // ---------------- Phase 1: stage inputs ----------------
    {   // edges -> u8 packed, 4 per u32
        const int4* ePtr = (const int4*)(edge_src + (size_t)g * NPG * DEG);
        for (int q = tid; q < 400; q += 512) {
            int4 e = ePtr[q];
            int b = g * NPG;
            sE8[q] = (u32)(e.x - b) | ((u32)(e.y - b) << 8) |
                     ((u32)(e.z - b) << 16) | ((u32)(e.w - b) << 24);
        }
    }
    {   // feat fp32 -> fp16 (row-major, 200 B/row)
        const float4* fsrc = (const float4*)(feat + (size_t)g * NPG * DIN);
        for (int i = tid; i < 2500; i += 512) {
            float4 f = fsrc[i];
            __half2 a = __floats2half2_rn(f.x, f.y);
            __half2 b = __floats2half2_rn(f.z, f.w);
            *(u64*)(sXh + i * 8) =
                (u64)(*reinterpret_cast<u32*>(&a)) |
                ((u64)(*reinterpret_cast<u32*>(&b)) << 32);
        }
    }
    // W1 -> fp16 quads (dims 4p..4p+3 in one u64)
    {
        const float4* wsrc = (const float4*)W1;
        for (int idx = tid; idx < 2500; idx += 512) {
            int o = idx / 25, p = idx - o * 25;
            float4 w = wsrc[o * 25 + p];
            __half2 a = __floats2half2_rn(w.x, w.y);
            __half2 b = __floats2half2_rn(w.z, w.w);
            sW1u[o * PW1 + p] =
                (u64)(*reinterpret_cast<u32*>(&a)) |
                ((u64)(*reinterpret_cast<u32*>(&b)) << 32);
        }
    }
    // W2 fp32 -> pitch 102
    for (int idx = tid; idx < DG * 50; idx += 512) {
        int o = idx / 50, kp = idx - o * 50;
        *(u64*)&sW2f[o * PW2 + 2 * kp] = *(const u64*)&W2[o * H1D + 2 * kp];
    }
    for (int i = tid; i < P2D; i += 512) sSf[i] = self_feat[g * P2D + i];
    for (int i = tid; i < P3D; i += 512) sX3[i] = x3d[g * P3D + i];
    __syncthreads();

    // ---------------- agg1: SUM of 16 nbrs (fp16 HADD2, 4 groups of 4) ------
    // /16 deferred to GEMM1 epilogue. Lane<25 handles dims 4*lane..4*lane+3.
    if (lane < 25) {
        #pragma unroll
        for (int i = 0; i < 7; ++i) {
            int n = warp + 16 * i;
            if (n < NPG) {
                uint4 ep = ((const uint4*)sE8)[n];
                u32 ew[4] = {ep.x, ep.y, ep.z, ep.w};
                __half2 g0[4], g1[4];
                #pragma unroll
                for (int q = 0; q < 4; ++q) {
                    g0[q] = __floats2half2_rn(0.f, 0.f);
                    g1[q] = g0[q];
                    #pragma unroll
                    for (int b = 0; b < 4; ++b) {
                        int s = (ew[q] >> (8 * b)) & 0xff;
                        u32 lo, hi;
                        lds_v2u32(lo, hi, sXh + s * 200 + lane * 8);
                        g0[q] = __hadd2(g0[q], asH2(lo));
                        g1[q] = __hadd2(g1[q], asH2(hi));
                    }
                }
                __half2 s0 = __hadd2(__hadd2(g0[0], g0[1]), __hadd2(g0[2], g0[3]));
                __half2 s1 = __hadd2(__hadd2(g1[0], g1[1]), __hadd2(g1[2], g1[3]));
                float2 f0 = __half22float2(s0);
                float2 f1 = __half22float2(s1);
                *(u64*)&sA[n * 100 + 4 * lane]     = pack2(f0.x, f0.y);
                *(u64*)&sA[n * 100 + 4 * lane + 2] = pack2(f1.x, f1.y);
            }
        }
    }
    __syncthreads();   // all feat reads done -> feat buffer reusable (h park)

    // ---------------- GEMM1: h1 = relu((A @ W1^T)/16 + b1) ------------------
    // Pass 0: cols {lane, lane+32}  -> packed fp16 into sH16 (dead feat buf)
    // Pass 1: cols {64+lane, 96+lane(<4)} -> epilogue writes ALL h1 into sA
    {
        const float inv16 = 1.f / 16.f;
        #pragma unroll 1
        for (int cp = 0; cp < 2; ++cp) {
            const int c0 = lane + 64 * cp;
            const int c1 = c0 + 32;
            const bool c1v = (c1 < H1D);
            const int c1r = c1v ? c1 : 0;

            u64 acc[7][2];
            #pragma unroll
            for (int i = 0; i < 7; ++i) { acc[i][0] = 0ull; acc[i][1] = 0ull; }

            #pragma unroll 2
            for (int p = 0; p < 25; ++p) {       // dims 4p..4p+3
                u64 wq0 = sW1u[c0 * PW1 + p];
                u64 wq1 = sW1u[c1r * PW1 + p];
                u64 w0a = h2w((u32)wq0), w0b = h2w((u32)(wq0 >> 32));
                u64 w1a = h2w((u32)wq1), w1b = h2w((u32)(wq1 >> 32));
                #pragma unroll
                for (int i = 0; i < 7; ++i) {
                    int rc = warp + 16 * i; rc = (rc < NPG) ? rc : (NPG - 1);
                    u64 vlo, vhi;
                    lds_v2u64(vlo, vhi, &sA[rc * 100 + 4 * p]);  // warp-uniform
                    ffma2(acc[i][0], vlo, w0a);
                    ffma2(acc[i][1], vlo, w1a);
                    ffma2(acc[i][0], vhi, w0b);
                    ffma2(acc[i][1], vhi, w1b);
                }
            }
            float bb0 = b1[c0];
            float bb1 = c1v ? b1[c1] : 0.f;
            if (cp == 0) {
                // park pass-0 results as fp16 pairs in the dead feat buffer
                #pragma unroll
                for (int i = 0; i < 7; ++i) {
                    int r = warp + 16 * i;
                    if (r < NPG) {
                        float v0 = fmaxf(fmaf(hsum2(acc[i][0]), inv16, bb0), 0.f);
                        float v1 = fmaxf(fmaf(hsum2(acc[i][1]), inv16, bb1), 0.f);
                        __half2 hp = __floats2half2_rn(v0, v1);
                        sH16[r * 32 + lane] = *reinterpret_cast<u32*>(&hp);
                    }
                }
            } else {
                // all A reads done -> write full h1 over sA (own rows only)
                #pragma unroll
                for (int i = 0; i < 7; ++i) {
                    int r = warp + 16 * i;
                    if (r < NPG) {
                        u32 hp = sH16[r * 32 + lane];
                        float2 f = __half22float2(asH2(hp));
                        sA[r * 100 + lane]      = f.x;
                        sA[r * 100 + lane + 32] = f.y;
                        sA[r * 100 + c0] =
                            fmaxf(fmaf(hsum2(acc[i][0]), inv16, bb0), 0.f);
                        if (c1v)
                            sA[r * 100 + c1] =
                                fmaxf(fmaf(hsum2(acc[i][1]), inv16, bb1), 0.f);
                    }
                }
            }
        }
    }
    __syncwarp();

    // ---------------- GEMM2: t = h1 @ W2^T (pre-bias) -> sA cols 0..19 ------
    {
        const int c = (lane < DG) ? lane : 0;
        u64 acc2[7];
        #pragma unroll
        for (int i = 0; i < 7; ++i) acc2[i] = 0ull;

        #pragma unroll 2
        for (int p = 0; p < 25; ++p) {
            u64 wa = *(const u64*)&sW2f[c * PW2 + 4 * p];
            u64 wb = *(const u64*)&sW2f[c * PW2 + 4 * p + 2];
            #pragma unroll
            for (int i = 0; i < 7; ++i) {
                int rc = warp + 16 * i; rc = (rc < NPG) ? rc : (NPG - 1);
                u64 vlo, vhi;
                lds_v2u64(vlo, vhi, &sA[rc * 100 + 4 * p]);   // h1 bc (own rows)
                ffma2(acc2[i], vlo, wa);
                ffma2(acc2[i], vhi, wb);
            }
        }
        if (lane < DG) {
            #pragma unroll
            for (int i = 0; i < 7; ++i) {
                int r = warp + 16 * i;
                if (r < NPG) sA[r * 100 + lane] = hsum2(acc2[i]);  // t overlay
            }
        }
    }
    __syncthreads();   // full t needed for aggregation 2

    // ---------------- agg2 + b2 + relu + graph-mean partial (fused) ---------
    {
        float b2l = (lane < DG) ? b2[lane] : 0.f;
        int cl = (lane < DG) ? lane : 0;
        float hacc = 0.f;
        #pragma unroll
        for (int i = 0; i < 7; ++i) {
            int n = warp + 16 * i;
            if (n < NPG) {
                uint4 ep = ((const uint4*)sE8)[n];
                u32 ew[4] = {ep.x, ep.y, ep.z, ep.w};
                float t2 = 0.f;
                #pragma unroll
                for (int q = 0; q < 4; ++q) {
                    #pragma unroll
                    for (int b = 0; b < 4; ++b) {
                        int s = (ew[q] >> (8 * b)) & 0xff;
                        t2 += sA[s * 100 + cl];
                    }
                }
                hacc += fmaxf(t2 * (1.f / DEG) + b2l, 0.f);
            }
        }
        if (lane < DG) sPart[warp * DG + lane] = hacc;
    }
    {   // attention V partials: 16 chunks
        int j  = lane;
        int pg = warp;
        {   // v2: 200 dims in 16 chunks of 13
            int p0 = pg * 13, p1 = min(p0 + 13, P2D);
            float acc = 0.f;
            for (int p = p0; p < p1; ++p) acc = fmaf(Wv2[j * P2D + p], sSf[p], acc);
            sVp2[pg * 32 + j] = acc;
        }
        {   // v3: 100 dims in 16 chunks of 7
            int p0 = pg * 7, p1 = min(p0 + 7, P3D);
            float acc = 0.f;
            for (int p = p0; p < p1; ++p) acc = fmaf(Wv3[j * P3D + p], sX3[p], acc);
            sVp3[pg * 32 + j] = acc;
        }
    }
    __syncthreads();

    // ---------------- head (warp 0) -----------------------------------------
    if (tid < 32) {
        float v2 = 0.f, v3 = 0.f;
        #pragma unroll
        for (int pg = 0; pg < 16; ++pg) {
            v2 += sVp2[pg * 32 + lane];
            v3 += sVp3[pg * 32 + lane];
        }
        sVv[lane]      = v2;
        sVv[32 + lane] = v3;
        __syncwarp();

        float hg = 0.f, z2 = 0.f;
        if (lane < DG) {
            #pragma unroll
            for (int w = 0; w < 16; ++w) hg += sPart[w * DG + lane];
            hg *= (1.f / NPG);
            #pragma unroll
            for (int j = 0; j < 32; ++j) z2 = fmaf(Wo2[lane * 32 + j], sVv[j], z2);
        }
        float y = hg + z2;
        float t = (lane < DG) ? y : 0.f;
        #pragma unroll
        for (int o = 16; o > 0; o >>= 1) t += __shfl_xor_sync(0xffffffffu, t, o);
        float mu = t * (1.f / DG);
        float dv = (lane < DG) ? (y - mu) : 0.f;
        float t2 = dv * dv;
        #pragma unroll
        for (int o = 16; o > 0; o >>= 1) t2 += __shfl_xor_sync(0xffffffffu, t2, o);
        float inv = rsqrtf(t2 * (1.f / DG) + 1e-5f);
        float hg1 = (lane < DG) ? fmaf((y - mu) * inv, g2[lane], be2[lane]) : 0.f;

        float z3 = 0.f;
        if (lane < DG) {
            #pragma unroll
            for (int j = 0; j < 32; ++j) z3 = fmaf(Wo3[lane * 32 + j], sVv[32 + j], z3);
        }
        float y2 = hg1 + z3;
        t = (lane < DG) ? y2 : 0.f;
        #pragma unroll
        for (int o = 16; o > 0; o >>= 1) t += __shfl_xor_sync(0xffffffffu, t, o);
        mu = t * (1.f / DG);
        dv = (lane < DG) ? (y2 - mu) : 0.f;
        t2 = dv * dv;
        #pragma unroll
        for (int o = 16; o > 0; o >>= 1) t2 += __shfl_xor_sync(0xffffffffu, t2, o);
        inv = rsqrtf(t2 * (1.f / DG) + 1e-5f);
        if (lane < DG) sHg2[lane] = fmaf((y2 - mu) * inv, g3[lane], be3[lane]);
        __syncwarp();

        if (lane < 10) {
            float a = bf1[lane];
            #pragma unroll
            for (int d = 0; d < DG; ++d) a = fmaf(Wf1[lane * DG + d], sHg2[d], a);
            sO10[lane] = fmaxf(a, 0.f);
        }
        __syncwarp();

        if (lane == 0) {
            float o = bf2[0];
            #pragma unroll
            for (int i = 0; i < 10; ++i) o = fmaf(Wf2[i], sO10[i], o);
            out[g] = o;
        }
    }
}

extern "C" void kernel_launch(void* const* d_in, const int* in_sizes, int n_in,
                              void* d_out, int out_size) {
    const float* feat     = (const float*)d_in[0];
    const int*   edge_src = (const int*)  d_in[1];
    // d_in[2] = edge_dst (implicit: repeat(arange))
    const float* self_f   = (const float*)d_in[3];
    const float* x3d      = (const float*)d_in[4];
    const float* W1  = (const float*)d_in[5];
    const float* b1  = (const float*)d_in[6];
    const float* W2  = (const float*)d_in[7];
    const float* b2  = (const float*)d_in[8];
    // 9 Wq2, 10 Wk2 unused (softmax over length-1 token == 1)
    const float* Wv2 = (const float*)d_in[11];
    const float* Wo2 = (const float*)d_in[12];
    const float* g2  = (const float*)d_in[13];
    const float* be2 = (const float*)d_in[14];
    // 15 Wq3, 16 Wk3 unused
    const float* Wv3 = (const float*)d_in[17];
    const float* Wo3 = (const float*)d_in[18];
    const float* g3  = (const float*)d_in[19];
    const float* be3 = (const float*)d_in[20];
    const float* Wf1 = (const float*)d_in[21];
    const float* bf1 = (const float*)d_in[22];
    const float* Wf2 = (const float*)d_in[23];
    const float* bf2 = (const float*)d_in[24];
    float* out = (float*)d_out;

    cudaFuncSetAttribute(net_kernel, cudaFuncAttributeMaxDynamicSharedMemorySize,
                         SMEM_BYTES);
    net_kernel<<<512, 512, SMEM_BYTES>>>(feat, edge_src, self_f, x3d,
                                         W1, b1, W2, b2,
                                         Wv2, Wo2, g2, be2,
                                         Wv3, Wo3, g3, be3,
                                         Wf1, bf1, Wf2, bf2, out);
}